// round 1
// baseline (speedup 1.0000x reference)
#include <cuda_runtime.h>
#include <math.h>

#define B_TOT 65536
#define EPS 1e-5f

// ---------------- scratch (static device globals; no runtime alloc) ----------
__device__ float g_K[(size_t)B_TOT * 2048];   // 512 MB
__device__ float g_V[(size_t)B_TOT * 2048];   // 512 MB
__device__ float g_sumK[64];
__device__ float g_sumK2[64];
__device__ float g_cmd[20];                   // [0..3] colsum, [4..19] 4x4 gram
__device__ float g_cst[256];                  // qmul, qadd, aK, cK (64 each)

// ---------------- zero the accumulators (fresh every launch) -----------------
__global__ void zero_stats_kernel() {
    int t = threadIdx.x;
    if (t < 64) { g_sumK[t] = 0.f; g_sumK2[t] = 0.f; }
    if (t < 20) { g_cmd[t] = 0.f; }
}

// ---------------- command column sums + 4x4 Gram (for Q BN stats) ------------
__global__ void cmd_stats_kernel(const float* __restrict__ command) {
    float s[4]  = {0.f, 0.f, 0.f, 0.f};
    float g[16] = {0.f};
    int stride = gridDim.x * blockDim.x;
    for (int b = blockIdx.x * blockDim.x + threadIdx.x; b < B_TOT; b += stride) {
        float4 c = *(const float4*)(command + (size_t)b * 4);
        float v[4] = {c.x, c.y, c.z, c.w};
        #pragma unroll
        for (int i = 0; i < 4; i++) {
            s[i] += v[i];
            #pragma unroll
            for (int j = 0; j < 4; j++) g[i * 4 + j] += v[i] * v[j];
        }
    }
    __shared__ float sh[20];
    if (threadIdx.x < 20) sh[threadIdx.x] = 0.f;
    __syncthreads();
    #pragma unroll
    for (int i = 0; i < 4; i++) atomicAdd(&sh[i], s[i]);
    #pragma unroll
    for (int i = 0; i < 16; i++) atomicAdd(&sh[4 + i], g[i]);
    __syncthreads();
    if (threadIdx.x < 20) atomicAdd(&g_cmd[threadIdx.x], sh[threadIdx.x]);
}

// ---------------- K/V projection GEMMs: C = X @ W^T (128x128x16 tiles) -------
// blockIdx.z (which): 0 = K lo (feature,Wkz)  1 = K hi (hidden,Wkh)
//                     2 = V lo (feature,Wvz)  3 = V hi (hidden,Wvh)
__global__ __launch_bounds__(256) void gemm_kv_kernel(
    const float* __restrict__ feature, const float* __restrict__ hidden,
    const float* __restrict__ Wkz, const float* __restrict__ Wkh,
    const float* __restrict__ Wvz, const float* __restrict__ Wvh)
{
    const int which = blockIdx.z;
    const float* __restrict__ X = (which & 1) ? hidden : feature;
    const float* __restrict__ W =
        (which == 0) ? Wkz : (which == 1) ? Wkh : (which == 2) ? Wvz : Wvh;
    float* C = (which < 2) ? g_K : g_V;
    const int jbase = (which & 1) ? 1024 : 0;

    const int row0 = blockIdx.y * 128;
    const int col0 = blockIdx.x * 128;
    const int tid  = threadIdx.x;

    __shared__ float As[16][128];   // [k][m]
    __shared__ float Ws[16][128];   // [k][n]

    float acc[8][8];
    #pragma unroll
    for (int i = 0; i < 8; i++)
        #pragma unroll
        for (int j = 0; j < 8; j++) acc[i][j] = 0.f;

    const int ldRow = tid >> 2;         // 0..63
    const int ldK   = (tid & 3) * 4;    // 0,4,8,12
    const int cRow  = (tid >> 4) * 8;   // 0..120
    const int cCol  = (tid & 15) * 8;   // 0..120

    for (int k0 = 0; k0 < 256; k0 += 16) {
        #pragma unroll
        for (int h = 0; h < 2; h++) {
            int rr = ldRow + 64 * h;
            float4 a4 = *(const float4*)(X + (size_t)(row0 + rr) * 256 + k0 + ldK);
            As[ldK + 0][rr] = a4.x; As[ldK + 1][rr] = a4.y;
            As[ldK + 2][rr] = a4.z; As[ldK + 3][rr] = a4.w;
            float4 w4 = *(const float4*)(W + (size_t)(col0 + rr) * 256 + k0 + ldK);
            Ws[ldK + 0][rr] = w4.x; Ws[ldK + 1][rr] = w4.y;
            Ws[ldK + 2][rr] = w4.z; Ws[ldK + 3][rr] = w4.w;
        }
        __syncthreads();
        #pragma unroll
        for (int k = 0; k < 16; k++) {
            float a[8], b[8];
            #pragma unroll
            for (int i = 0; i < 8; i++) a[i] = As[k][cRow + i];
            #pragma unroll
            for (int j = 0; j < 8; j++) b[j] = Ws[k][cCol + j];
            #pragma unroll
            for (int i = 0; i < 8; i++)
                #pragma unroll
                for (int j = 0; j < 8; j++) acc[i][j] += a[i] * b[j];
        }
        __syncthreads();
    }

    // write C tile (K or V), vectorized
    #pragma unroll
    for (int i = 0; i < 8; i++) {
        size_t base = (size_t)(row0 + cRow + i) * 2048 + jbase + col0 + cCol;
        float4 o0 = make_float4(acc[i][0], acc[i][1], acc[i][2], acc[i][3]);
        float4 o1 = make_float4(acc[i][4], acc[i][5], acc[i][6], acc[i][7]);
        *(float4*)(C + base)     = o0;
        *(float4*)(C + base + 4) = o1;
    }

    // K BatchNorm statistics: d = j mod 64; hierarchical reduction
    if (which < 2) {
        __shared__ float sS[64], sS2[64];
        if (tid < 64) { sS[tid] = 0.f; sS2[tid] = 0.f; }
        __syncthreads();
        #pragma unroll
        for (int j = 0; j < 8; j++) {
            int d = (cCol + j) & 63;   // col0, jbase are multiples of 128
            float s = 0.f, s2 = 0.f;
            #pragma unroll
            for (int i = 0; i < 8; i++) { float v = acc[i][j]; s += v; s2 += v * v; }
            atomicAdd(&sS[d], s);
            atomicAdd(&sS2[d], s2);
        }
        __syncthreads();
        if (tid < 64) {
            atomicAdd(&g_sumK[tid], sS[tid]);
            atomicAdd(&g_sumK2[tid], sS2[tid]);
        }
    }
}

// ---------------- fold BN stats into per-d affine constants ------------------
__global__ void finalize_kernel(const float* __restrict__ Wq,
                                const float* __restrict__ gammaQ,
                                const float* __restrict__ betaQ,
                                const float* __restrict__ gammaK,
                                const float* __restrict__ betaK)
{
    int d = threadIdx.x;
    if (d >= 64) return;
    const float invB = 1.f / 65536.f;

    float w[4];
    #pragma unroll
    for (int c = 0; c < 4; c++) w[c] = Wq[d * 4 + c];

    // Q stats analytically from command stats (Q linear in command)
    float mQ = 0.f;
    #pragma unroll
    for (int c = 0; c < 4; c++) mQ += (g_cmd[c] * invB) * w[c];
    float eq2 = 0.f;
    #pragma unroll
    for (int c1 = 0; c1 < 4; c1++)
        #pragma unroll
        for (int c2 = 0; c2 < 4; c2++)
            eq2 += w[c1] * w[c2] * g_cmd[4 + c1 * 4 + c2];
    eq2 *= invB;
    float vQ = eq2 - mQ * mQ;
    float gq = gammaQ[d] / sqrtf(vQ + EPS);
    g_cst[d]      = gq;                       // qmul
    g_cst[64 + d] = betaQ[d] - mQ * gq;       // qadd

    // K stats from GEMM-epilogue accumulation
    const float invBF = 1.f / (65536.f * 32.f);
    float mK = g_sumK[d] * invBF;
    float vK = g_sumK2[d] * invBF - mK * mK;
    float aK = gammaK[d] / sqrtf(vK + EPS);
    g_cst[128 + d] = aK;                      // K scale
    g_cst[192 + d] = betaK[d] - mK * aK;      // K shift
}

// ---------------- attention: 1 warp per batch row -----------------------------
__global__ __launch_bounds__(256) void attn_kernel(
    const float* __restrict__ command, const float* __restrict__ Wq,
    float* __restrict__ out)
{
    __shared__ float sh_qa[8][64];
    const int w    = threadIdx.x >> 5;
    const int lane = threadIdx.x & 31;
    const int b    = blockIdx.x * 8 + w;

    float4 c4 = *(const float4*)(command + (size_t)b * 4);
    const int d0 = lane, d1 = lane + 32;

    float q0 = c4.x * Wq[d0 * 4 + 0] + c4.y * Wq[d0 * 4 + 1] +
               c4.z * Wq[d0 * 4 + 2] + c4.w * Wq[d0 * 4 + 3];
    float q1 = c4.x * Wq[d1 * 4 + 0] + c4.y * Wq[d1 * 4 + 1] +
               c4.z * Wq[d1 * 4 + 2] + c4.w * Wq[d1 * 4 + 3];
    float qn0 = q0 * g_cst[d0] + g_cst[64 + d0];
    float qn1 = q1 * g_cst[d1] + g_cst[64 + d1];

    float qa0 = qn0 * g_cst[128 + d0];
    float qa1 = qn1 * g_cst[128 + d1];
    float qc  = qn0 * g_cst[192 + d0] + qn1 * g_cst[192 + d1];
    #pragma unroll
    for (int o = 16; o; o >>= 1) qc += __shfl_xor_sync(0xffffffffu, qc, o);

    sh_qa[w][d0] = qa0;
    sh_qa[w][d1] = qa1;
    __syncwarp();

    // logit for f = lane: dot(qa, K[b, f*64 .. f*64+63])  (K row contiguous)
    const float4* Kr = (const float4*)(g_K + (size_t)b * 2048 + lane * 64);
    float acc = 0.f;
    #pragma unroll
    for (int t = 0; t < 16; t++) {
        float4 k4 = Kr[t];
        acc += sh_qa[w][4 * t + 0] * k4.x + sh_qa[w][4 * t + 1] * k4.y +
               sh_qa[w][4 * t + 2] * k4.z + sh_qa[w][4 * t + 3] * k4.w;
    }
    float logit = (acc + qc) * 0.125f;   // 1/sqrt(64)

    // softmax over the 32 lanes (f dimension)
    float mx = logit;
    #pragma unroll
    for (int o = 16; o; o >>= 1) mx = fmaxf(mx, __shfl_xor_sync(0xffffffffu, mx, o));
    float e = __expf(logit - mx);
    float den = e;
    #pragma unroll
    for (int o = 16; o; o >>= 1) den += __shfl_xor_sync(0xffffffffu, den, o);
    float a = e / den;

    // s[b,d] = sum_f A[f] * V[b, f*64 + d]  (coalesced across lanes)
    const float* Vr = g_V + (size_t)b * 2048;
    float s0 = 0.f, s1 = 0.f;
    #pragma unroll
    for (int f = 0; f < 32; f++) {
        float af = __shfl_sync(0xffffffffu, a, f);
        s0 += af * Vr[f * 64 + d0];
        s1 += af * Vr[f * 64 + d1];
    }
    out[(size_t)b * 64 + d0] = s0;
    out[(size_t)b * 64 + d1] = s1;
}

// ---------------- launch ------------------------------------------------------
extern "C" void kernel_launch(void* const* d_in, const int* in_sizes, int n_in,
                              void* d_out, int out_size)
{
    const float* feature = (const float*)d_in[0];
    const float* hidden  = (const float*)d_in[1];
    const float* command = (const float*)d_in[2];
    const float* Wq      = (const float*)d_in[3];
    const float* Wkz     = (const float*)d_in[4];
    const float* Wkh     = (const float*)d_in[5];
    const float* Wvz     = (const float*)d_in[6];
    const float* Wvh     = (const float*)d_in[7];
    const float* gammaQ  = (const float*)d_in[8];
    const float* betaQ   = (const float*)d_in[9];
    const float* gammaK  = (const float*)d_in[10];
    const float* betaK   = (const float*)d_in[11];
    float* out = (float*)d_out;

    zero_stats_kernel<<<1, 64>>>();
    cmd_stats_kernel<<<128, 256>>>(command);
    gemm_kv_kernel<<<dim3(8, 512, 4), 256>>>(feature, hidden, Wkz, Wkh, Wvz, Wvh);
    finalize_kernel<<<1, 64>>>(Wq, gammaQ, betaQ, gammaK, betaK);
    attn_kernel<<<B_TOT / 8, 256>>>(command, Wq, out);
}

// round 3
// speedup vs baseline: 2.1225x; 2.1225x over previous
#include <cuda_runtime.h>
#include <cuda_bf16.h>
#include <cstdint>
#include <math.h>

#define B_TOT 65536
#define EPS 1e-5f
#define NXF (65536 * 256)          // floats per X plane
#define NWF (1024 * 256)           // floats per W plane

// ---------------- scratch (static device globals; no runtime alloc) ----------
__device__ float g_K[(size_t)B_TOT * 2048];            // 512 MB
__device__ float g_V[(size_t)B_TOT * 2048];            // 512 MB
__device__ __nv_bfloat16 g_Xhi[(size_t)2 * NXF];       // 64 MB
__device__ __nv_bfloat16 g_Xlo[(size_t)2 * NXF];       // 64 MB
__device__ __nv_bfloat16 g_Whi[(size_t)4 * NWF];       // 2 MB
__device__ __nv_bfloat16 g_Wlo[(size_t)4 * NWF];       // 2 MB
__device__ float g_sumK[64];
__device__ float g_sumK2[64];
__device__ float g_cmd[20];
__device__ float g_cst[256];

// ================= PTX helpers (sm_80-era only; safe on plain sm_103) ========
__device__ __forceinline__ uint32_t smem_u32(const void* p) {
    uint32_t a;
    asm("{ .reg .u64 t; cvta.to.shared.u64 t, %1; cvt.u32.u64 %0, t; }" : "=r"(a) : "l"(p));
    return a;
}
#define CP16(dst, src) \
    asm volatile("cp.async.cg.shared.global [%0], [%1], 16;" :: "r"(dst), "l"(src))
#define CP_COMMIT() asm volatile("cp.async.commit_group;")
#define CP_WAIT1()  asm volatile("cp.async.wait_group 1;")
#define CP_WAIT0()  asm volatile("cp.async.wait_group 0;")

#define LDSM4(r0, r1, r2, r3, addr) \
    asm volatile("ldmatrix.sync.aligned.m8n8.x4.shared.b16 {%0,%1,%2,%3}, [%4];" \
                 : "=r"(r0), "=r"(r1), "=r"(r2), "=r"(r3) : "r"(addr))

#define MMA16816(d, a, b0, b1) \
    asm volatile("mma.sync.aligned.m16n8k16.row.col.f32.bf16.bf16.f32 " \
                 "{%0,%1,%2,%3},{%4,%5,%6,%7},{%8,%9},{%0,%1,%2,%3};" \
                 : "+f"((d)[0]), "+f"((d)[1]), "+f"((d)[2]), "+f"((d)[3]) \
                 : "r"((a)[0]), "r"((a)[1]), "r"((a)[2]), "r"((a)[3]), \
                   "r"(b0), "r"(b1))

// ---------------- zero the accumulators --------------------------------------
__global__ void zero_stats_kernel() {
    int t = threadIdx.x;
    if (t < 64) { g_sumK[t] = 0.f; g_sumK2[t] = 0.f; }
    if (t < 20) { g_cmd[t] = 0.f; }
}

// ---------------- command column sums + 4x4 Gram ------------------------------
__global__ void cmd_stats_kernel(const float* __restrict__ command) {
    float s[4]  = {0.f, 0.f, 0.f, 0.f};
    float g[16] = {0.f};
    int stride = gridDim.x * blockDim.x;
    for (int b = blockIdx.x * blockDim.x + threadIdx.x; b < B_TOT; b += stride) {
        float4 c = *(const float4*)(command + (size_t)b * 4);
        float v[4] = {c.x, c.y, c.z, c.w};
        #pragma unroll
        for (int i = 0; i < 4; i++) {
            s[i] += v[i];
            #pragma unroll
            for (int j = 0; j < 4; j++) g[i * 4 + j] += v[i] * v[j];
        }
    }
    __shared__ float sh[20];
    if (threadIdx.x < 20) sh[threadIdx.x] = 0.f;
    __syncthreads();
    #pragma unroll
    for (int i = 0; i < 4; i++) atomicAdd(&sh[i], s[i]);
    #pragma unroll
    for (int i = 0; i < 16; i++) atomicAdd(&sh[4 + i], g[i]);
    __syncthreads();
    if (threadIdx.x < 20) atomicAdd(&g_cmd[threadIdx.x], sh[threadIdx.x]);
}

// ---------------- split fp32 -> bf16 hi/lo planes -----------------------------
__global__ __launch_bounds__(256) void split_kernel(
    const float* __restrict__ f, const float* __restrict__ h,
    const float* __restrict__ wkz, const float* __restrict__ wkh,
    const float* __restrict__ wvz, const float* __restrict__ wvh)
{
    const size_t NX4 = (size_t)2 * NXF / 4;   // X threads (4 floats each)
    size_t gid = (size_t)blockIdx.x * 256 + threadIdx.x;

    const float* src;
    __nv_bfloat16 *dhi, *dlo;
    size_t base;
    if (gid < NX4) {
        base = gid * 4;
        src  = (base < (size_t)NXF) ? (f + base) : (h + (base - NXF));
        dhi  = g_Xhi + base; dlo = g_Xlo + base;
    } else {
        size_t wi = gid - NX4;
        base = wi * 4;
        size_t o = base;
        if      (o < (size_t)NWF)     src = wkz + o;
        else if (o < (size_t)2*NWF)   src = wkh + (o - NWF);
        else if (o < (size_t)3*NWF)   src = wvz + (o - 2*(size_t)NWF);
        else                          src = wvh + (o - 3*(size_t)NWF);
        dhi = g_Whi + base; dlo = g_Wlo + base;
    }
    float4 v = *(const float4*)src;
    float vv[4] = {v.x, v.y, v.z, v.w};
    ushort4 uh, ul;
    unsigned short* ph = (unsigned short*)&uh;
    unsigned short* pl = (unsigned short*)&ul;
    #pragma unroll
    for (int i = 0; i < 4; i++) {
        __nv_bfloat16 hi = __float2bfloat16(vv[i]);
        __nv_bfloat16 lo = __float2bfloat16(vv[i] - __bfloat162float(hi));
        ph[i] = __bfloat16_as_ushort(hi);
        pl[i] = __bfloat16_as_ushort(lo);
    }
    *(ushort4*)dhi = uh;
    *(ushort4*)dlo = ul;
}

// =============================================================================
// HMMA bf16x3 GEMM:  C_tile[128 x 256] = X[128,256] @ W^T slice
// grid (4 Ntiles, 512 Mtiles, 4 which), 256 threads (8 warps, warp tile 64x64)
// smem per stage: Ahi|Alo (2x16KB) + Bhi|Blo (2x32KB) = 96KB, 2 stages = 192KB
// =============================================================================
#define STAGE_B 98304
#define GEMM_SMEM (2 * STAGE_B)

__global__ __launch_bounds__(256, 1) void gemm_mma_kernel()
{
    extern __shared__ char sm[];
    const uint32_t sb = smem_u32(sm);

    const int which = blockIdx.z;
    const __nv_bfloat16* __restrict__ Xhi = g_Xhi + (size_t)(which & 1) * NXF;
    const __nv_bfloat16* __restrict__ Xlo = g_Xlo + (size_t)(which & 1) * NXF;
    const __nv_bfloat16* __restrict__ Whi = g_Whi + (size_t)which * NWF;
    const __nv_bfloat16* __restrict__ Wlo = g_Wlo + (size_t)which * NWF;
    float* C = (which < 2) ? g_K : g_V;
    const int jb   = (which & 1) ? 1024 : 0;
    const int row0 = blockIdx.y * 128;
    const int col0 = blockIdx.x * 256;

    const int tid  = threadIdx.x;
    const int warp = tid >> 5;
    const int lane = tid & 31;
    const int wm   = (warp >> 2) * 64;   // warp M origin (0 or 64)
    const int wn   = (warp & 3) * 64;    // warp N origin (0..192)

    __shared__ float sd[64], sd2[64];
    if (tid < 64) { sd[tid] = 0.f; sd2[tid] = 0.f; }

    float acc[4][8][4];
    #pragma unroll
    for (int a = 0; a < 4; a++)
        #pragma unroll
        for (int b = 0; b < 8; b++)
            #pragma unroll
            for (int c = 0; c < 4; c++) acc[a][b][c] = 0.f;

    // ---- cp.async issue of k-chunk kc into stage st --------------------------
    const int lr = tid >> 1;            // 0..127
    const int cb = (tid & 1) * 4;       // chunk base (of 8 x 16B per 128B row)
    auto issue = [&](int kc, int st) {
        uint32_t stg = sb + st * STAGE_B;
        // A planes: row lr, chunks cb..cb+3
        {
            const __nv_bfloat16* s0 = Xhi + (size_t)(row0 + lr) * 256 + kc * 64 + cb * 8;
            const __nv_bfloat16* s1 = Xlo + (size_t)(row0 + lr) * 256 + kc * 64 + cb * 8;
            uint32_t d0 = stg + lr * 128;
            #pragma unroll
            for (int q = 0; q < 4; q++) {
                uint32_t sw = ((cb + q) ^ (lr & 7)) << 4;
                CP16(d0 + sw,         s0 + q * 8);
                CP16(d0 + 16384 + sw, s1 + q * 8);
            }
        }
        // B planes: rows lr and lr+128
        #pragma unroll
        for (int hh = 0; hh < 2; hh++) {
            int r = lr + hh * 128;
            const __nv_bfloat16* s0 = Whi + (size_t)(col0 + r) * 256 + kc * 64 + cb * 8;
            const __nv_bfloat16* s1 = Wlo + (size_t)(col0 + r) * 256 + kc * 64 + cb * 8;
            uint32_t d0 = stg + 32768 + r * 128;
            #pragma unroll
            for (int q = 0; q < 4; q++) {
                uint32_t sw = ((cb + q) ^ (r & 7)) << 4;
                CP16(d0 + sw,         s0 + q * 8);
                CP16(d0 + 32768 + sw, s1 + q * 8);
            }
        }
    };

    issue(0, 0); CP_COMMIT();
    issue(1, 1); CP_COMMIT();

    for (int c = 0; c < 4; c++) {
        if (c < 3) { CP_WAIT1(); } else { CP_WAIT0(); }
        __syncthreads();

        const uint32_t stg = sb + (c & 1) * STAGE_B;
        #pragma unroll
        for (int k16 = 0; k16 < 4; k16++) {
            // A fragments (hi & lo), 4 M-frags
            uint32_t ah[4][4], al[4][4];
            #pragma unroll
            for (int mf = 0; mf < 4; mf++) {
                int r = wm + mf * 16 + (lane & 15);
                int ch = 2 * k16 + (lane >> 4);
                uint32_t ad = stg + r * 128 + ((ch ^ (r & 7)) << 4);
                LDSM4(ah[mf][0], ah[mf][1], ah[mf][2], ah[mf][3], ad);
                LDSM4(al[mf][0], al[mf][1], al[mf][2], al[mf][3], ad + 16384);
            }
            // B: 4 groups of 16 n-cols; each LDSM4 gives 2 n-frags
            #pragma unroll
            for (int j = 0; j < 4; j++) {
                int r = wn + j * 16 + (lane & 15);
                int ch = 2 * k16 + (lane >> 4);
                uint32_t bd = stg + 32768 + r * 128 + ((ch ^ (r & 7)) << 4);
                uint32_t bh0, bh1, bh2, bh3, bl0, bl1, bl2, bl3;
                LDSM4(bh0, bh1, bh2, bh3, bd);
                LDSM4(bl0, bl1, bl2, bl3, bd + 32768);
                #pragma unroll
                for (int mf = 0; mf < 4; mf++) {
                    MMA16816(acc[mf][2 * j],     ah[mf], bh0, bh2);  // hi*hi
                    MMA16816(acc[mf][2 * j + 1], ah[mf], bh1, bh3);
                    MMA16816(acc[mf][2 * j],     ah[mf], bl0, bl2);  // hi*lo
                    MMA16816(acc[mf][2 * j + 1], ah[mf], bl1, bl3);
                    MMA16816(acc[mf][2 * j],     al[mf], bh0, bh2);  // lo*hi
                    MMA16816(acc[mf][2 * j + 1], al[mf], bh1, bh3);
                }
            }
        }
        __syncthreads();
        if (c + 2 < 4) { issue(c + 2, c & 1); CP_COMMIT(); }
    }

    // ---------------- epilogue: direct coalesced stores + K stats -------------
    const int rlo   = lane >> 2;
    const int cpair = (lane & 3) * 2;
    #pragma unroll
    for (int mf = 0; mf < 4; mf++) {
        #pragma unroll
        for (int nf = 0; nf < 8; nf++) {
            int row = row0 + wm + mf * 16 + rlo;
            int col = jb + col0 + wn + nf * 8 + cpair;
            float2 v01 = make_float2(acc[mf][nf][0], acc[mf][nf][1]);
            float2 v23 = make_float2(acc[mf][nf][2], acc[mf][nf][3]);
            *(float2*)(C + (size_t)row * 2048 + col)       = v01;
            *(float2*)(C + (size_t)(row + 8) * 2048 + col) = v23;
        }
    }
    if (which < 2) {
        __syncthreads();   // sd/sd2 zeroed
        #pragma unroll
        for (int nf = 0; nf < 8; nf++) {
            float s0 = 0.f, s1 = 0.f, q0 = 0.f, q1 = 0.f;
            #pragma unroll
            for (int mf = 0; mf < 4; mf++) {
                float a0 = acc[mf][nf][0], a1 = acc[mf][nf][1];
                float a2 = acc[mf][nf][2], a3 = acc[mf][nf][3];
                s0 += a0 + a2;  s1 += a1 + a3;
                q0 += a0 * a0 + a2 * a2;
                q1 += a1 * a1 + a3 * a3;
            }
            #pragma unroll
            for (int o = 4; o <= 16; o <<= 1) {
                s0 += __shfl_xor_sync(0xffffffffu, s0, o);
                s1 += __shfl_xor_sync(0xffffffffu, s1, o);
                q0 += __shfl_xor_sync(0xffffffffu, q0, o);
                q1 += __shfl_xor_sync(0xffffffffu, q1, o);
            }
            if (lane < 4) {
                int d = (wn + nf * 8 + lane * 2) & 63;
                atomicAdd(&sd[d], s0);      atomicAdd(&sd[d + 1], s1);
                atomicAdd(&sd2[d], q0);     atomicAdd(&sd2[d + 1], q1);
            }
        }
        __syncthreads();
        if (tid < 64) {
            atomicAdd(&g_sumK[tid], sd[tid]);
            atomicAdd(&g_sumK2[tid], sd2[tid]);
        }
    }
}

// ---------------- fold BN stats into per-d affine constants ------------------
__global__ void finalize_kernel(const float* __restrict__ Wq,
                                const float* __restrict__ gammaQ,
                                const float* __restrict__ betaQ,
                                const float* __restrict__ gammaK,
                                const float* __restrict__ betaK)
{
    int d = threadIdx.x;
    if (d >= 64) return;
    const float invB = 1.f / 65536.f;

    float w[4];
    #pragma unroll
    for (int c = 0; c < 4; c++) w[c] = Wq[d * 4 + c];

    float mQ = 0.f;
    #pragma unroll
    for (int c = 0; c < 4; c++) mQ += (g_cmd[c] * invB) * w[c];
    float eq2 = 0.f;
    #pragma unroll
    for (int c1 = 0; c1 < 4; c1++)
        #pragma unroll
        for (int c2 = 0; c2 < 4; c2++)
            eq2 += w[c1] * w[c2] * g_cmd[4 + c1 * 4 + c2];
    eq2 *= invB;
    float vQ = eq2 - mQ * mQ;
    float gq = gammaQ[d] / sqrtf(vQ + EPS);
    g_cst[d]      = gq;
    g_cst[64 + d] = betaQ[d] - mQ * gq;

    const float invBF = 1.f / (65536.f * 32.f);
    float mK = g_sumK[d] * invBF;
    float vK = g_sumK2[d] * invBF - mK * mK;
    float aK = gammaK[d] / sqrtf(vK + EPS);
    g_cst[128 + d] = aK;
    g_cst[192 + d] = betaK[d] - mK * aK;
}

// ---------------- attention: 1 warp per batch row -----------------------------
__global__ __launch_bounds__(256) void attn_kernel(
    const float* __restrict__ command, const float* __restrict__ Wq,
    float* __restrict__ out)
{
    __shared__ float sh_qa[8][64];
    const int w    = threadIdx.x >> 5;
    const int lane = threadIdx.x & 31;
    const int b    = blockIdx.x * 8 + w;

    float4 c4 = *(const float4*)(command + (size_t)b * 4);
    const int d0 = lane, d1 = lane + 32;

    float q0 = c4.x * Wq[d0 * 4 + 0] + c4.y * Wq[d0 * 4 + 1] +
               c4.z * Wq[d0 * 4 + 2] + c4.w * Wq[d0 * 4 + 3];
    float q1 = c4.x * Wq[d1 * 4 + 0] + c4.y * Wq[d1 * 4 + 1] +
               c4.z * Wq[d1 * 4 + 2] + c4.w * Wq[d1 * 4 + 3];
    float qn0 = q0 * g_cst[d0] + g_cst[64 + d0];
    float qn1 = q1 * g_cst[d1] + g_cst[64 + d1];

    float qa0 = qn0 * g_cst[128 + d0];
    float qa1 = qn1 * g_cst[128 + d1];
    float qc  = qn0 * g_cst[192 + d0] + qn1 * g_cst[192 + d1];
    #pragma unroll
    for (int o = 16; o; o >>= 1) qc += __shfl_xor_sync(0xffffffffu, qc, o);

    sh_qa[w][d0] = qa0;
    sh_qa[w][d1] = qa1;
    __syncwarp();

    const float4* Kr = (const float4*)(g_K + (size_t)b * 2048 + lane * 64);
    float acc = 0.f;
    #pragma unroll
    for (int t = 0; t < 16; t++) {
        float4 k4 = Kr[t];
        acc += sh_qa[w][4 * t + 0] * k4.x + sh_qa[w][4 * t + 1] * k4.y +
               sh_qa[w][4 * t + 2] * k4.z + sh_qa[w][4 * t + 3] * k4.w;
    }
    float logit = (acc + qc) * 0.125f;

    float mx = logit;
    #pragma unroll
    for (int o = 16; o; o >>= 1) mx = fmaxf(mx, __shfl_xor_sync(0xffffffffu, mx, o));
    float e = __expf(logit - mx);
    float den = e;
    #pragma unroll
    for (int o = 16; o; o >>= 1) den += __shfl_xor_sync(0xffffffffu, den, o);
    float a = e / den;

    const float* Vr = g_V + (size_t)b * 2048;
    float s0 = 0.f, s1 = 0.f;
    #pragma unroll
    for (int f = 0; f < 32; f++) {
        float af = __shfl_sync(0xffffffffu, a, f);
        s0 += af * Vr[f * 64 + d0];
        s1 += af * Vr[f * 64 + d1];
    }
    out[(size_t)b * 64 + d0] = s0;
    out[(size_t)b * 64 + d1] = s1;
}

// ---------------- launch ------------------------------------------------------
extern "C" void kernel_launch(void* const* d_in, const int* in_sizes, int n_in,
                              void* d_out, int out_size)
{
    const float* feature = (const float*)d_in[0];
    const float* hidden  = (const float*)d_in[1];
    const float* command = (const float*)d_in[2];
    const float* Wq      = (const float*)d_in[3];
    const float* Wkz     = (const float*)d_in[4];
    const float* Wkh     = (const float*)d_in[5];
    const float* Wvz     = (const float*)d_in[6];
    const float* Wvh     = (const float*)d_in[7];
    const float* gammaQ  = (const float*)d_in[8];
    const float* betaQ   = (const float*)d_in[9];
    const float* gammaK  = (const float*)d_in[10];
    const float* betaK   = (const float*)d_in[11];
    float* out = (float*)d_out;

    cudaFuncSetAttribute(gemm_mma_kernel,
                         cudaFuncAttributeMaxDynamicSharedMemorySize, GEMM_SMEM);

    zero_stats_kernel<<<1, 64>>>();
    cmd_stats_kernel<<<128, 256>>>(command);
    split_kernel<<<33792, 256>>>(feature, hidden, Wkz, Wkh, Wvz, Wvh);
    gemm_mma_kernel<<<dim3(4, 512, 4), 256, GEMM_SMEM>>>();
    finalize_kernel<<<1, 64>>>(Wq, gammaQ, betaQ, gammaK, betaK);
    attn_kernel<<<B_TOT / 8, 256>>>(command, Wq, out);
}

// round 4
// speedup vs baseline: 2.5829x; 1.2169x over previous
#include <cuda_runtime.h>
#include <cuda_fp16.h>
#include <cstdint>
#include <math.h>

#define B_TOT 65536
#define EPS 1e-5f
#define NXF (65536 * 256)          // floats per X plane
#define NWF (1024 * 256)           // floats per W plane

// ---------------- scratch (static device globals; no runtime alloc) ----------
__device__ float g_K[(size_t)B_TOT * 2048];            // 512 MB
__device__ float g_V[(size_t)B_TOT * 2048];            // 512 MB
__device__ __half g_Xhi[(size_t)2 * NXF];              // 64 MB
__device__ __half g_Xlo[(size_t)2 * NXF];              // 64 MB
__device__ __half g_Whi[(size_t)4 * NWF];              // 2 MB
__device__ float g_sumK[64];
__device__ float g_sumK2[64];
__device__ float g_cmd[20];
__device__ float g_cst[256];

// ================= PTX helpers (sm_80-era; safe on plain sm_103) =============
__device__ __forceinline__ uint32_t smem_u32(const void* p) {
    uint32_t a;
    asm("{ .reg .u64 t; cvta.to.shared.u64 t, %1; cvt.u32.u64 %0, t; }" : "=r"(a) : "l"(p));
    return a;
}
#define CP16(dst, src) \
    asm volatile("cp.async.cg.shared.global [%0], [%1], 16;" :: "r"(dst), "l"(src))
#define CP_COMMIT() asm volatile("cp.async.commit_group;")
#define CP_WAIT1()  asm volatile("cp.async.wait_group 1;")
#define CP_WAIT0()  asm volatile("cp.async.wait_group 0;")

#define LDSM4(r0, r1, r2, r3, addr) \
    asm volatile("ldmatrix.sync.aligned.m8n8.x4.shared.b16 {%0,%1,%2,%3}, [%4];" \
                 : "=r"(r0), "=r"(r1), "=r"(r2), "=r"(r3) : "r"(addr))

#define MMA16816(d, a, b0, b1) \
    asm volatile("mma.sync.aligned.m16n8k16.row.col.f32.f16.f16.f32 " \
                 "{%0,%1,%2,%3},{%4,%5,%6,%7},{%8,%9},{%0,%1,%2,%3};" \
                 : "+f"((d)[0]), "+f"((d)[1]), "+f"((d)[2]), "+f"((d)[3]) \
                 : "r"((a)[0]), "r"((a)[1]), "r"((a)[2]), "r"((a)[3]), \
                   "r"(b0), "r"(b1))

// ---------------- zero the accumulators --------------------------------------
__global__ void zero_stats_kernel() {
    int t = threadIdx.x;
    if (t < 64) { g_sumK[t] = 0.f; g_sumK2[t] = 0.f; }
    if (t < 20) { g_cmd[t] = 0.f; }
}

// ---------------- command column sums + 4x4 Gram ------------------------------
__global__ void cmd_stats_kernel(const float* __restrict__ command) {
    float s[4]  = {0.f, 0.f, 0.f, 0.f};
    float g[16] = {0.f};
    int stride = gridDim.x * blockDim.x;
    for (int b = blockIdx.x * blockDim.x + threadIdx.x; b < B_TOT; b += stride) {
        float4 c = *(const float4*)(command + (size_t)b * 4);
        float v[4] = {c.x, c.y, c.z, c.w};
        #pragma unroll
        for (int i = 0; i < 4; i++) {
            s[i] += v[i];
            #pragma unroll
            for (int j = 0; j < 4; j++) g[i * 4 + j] += v[i] * v[j];
        }
    }
    __shared__ float sh[20];
    if (threadIdx.x < 20) sh[threadIdx.x] = 0.f;
    __syncthreads();
    #pragma unroll
    for (int i = 0; i < 4; i++) atomicAdd(&sh[i], s[i]);
    #pragma unroll
    for (int i = 0; i < 16; i++) atomicAdd(&sh[4 + i], g[i]);
    __syncthreads();
    if (threadIdx.x < 20) atomicAdd(&g_cmd[threadIdx.x], sh[threadIdx.x]);
}

// ---------------- split: X -> fp16 hi+lo planes, W -> fp16 hi -----------------
__global__ __launch_bounds__(256) void split_kernel(
    const float* __restrict__ f, const float* __restrict__ h,
    const float* __restrict__ wkz, const float* __restrict__ wkh,
    const float* __restrict__ wvz, const float* __restrict__ wvh)
{
    const size_t NX4 = (size_t)2 * NXF / 4;
    size_t gid = (size_t)blockIdx.x * 256 + threadIdx.x;

    if (gid < NX4) {
        size_t base = gid * 4;
        const float* src = (base < (size_t)NXF) ? (f + base) : (h + (base - NXF));
        float4 v = *(const float4*)src;
        float vv[4] = {v.x, v.y, v.z, v.w};
        ushort4 uh, ul;
        unsigned short* ph = (unsigned short*)&uh;
        unsigned short* pl = (unsigned short*)&ul;
        #pragma unroll
        for (int i = 0; i < 4; i++) {
            __half hi = __float2half_rn(vv[i]);
            __half lo = __float2half_rn(vv[i] - __half2float(hi));
            ph[i] = __half_as_ushort(hi);
            pl[i] = __half_as_ushort(lo);
        }
        *(ushort4*)(g_Xhi + base) = uh;
        *(ushort4*)(g_Xlo + base) = ul;
    } else {
        size_t base = (gid - NX4) * 4;
        size_t o = base;
        const float* src;
        if      (o < (size_t)NWF)       src = wkz + o;
        else if (o < (size_t)2 * NWF)   src = wkh + (o - NWF);
        else if (o < (size_t)3 * NWF)   src = wvz + (o - 2 * (size_t)NWF);
        else                            src = wvh + (o - 3 * (size_t)NWF);
        float4 v = *(const float4*)src;
        float vv[4] = {v.x, v.y, v.z, v.w};
        ushort4 uh;
        unsigned short* ph = (unsigned short*)&uh;
        #pragma unroll
        for (int i = 0; i < 4; i++)
            ph[i] = __half_as_ushort(__float2half_rn(vv[i]));
        *(ushort4*)(g_Whi + base) = uh;
    }
}

// =============================================================================
// HMMA fp16 2-term GEMM, block-persistent.
// 1024 CTAs; CTA b owns row-block r0=(b>>1)*128, parity p=b&1.
// Block = 8 tiles: which in {p, p+2} x 4 col-tiles of 256; A shared by all 8.
// 32 chunks (K=256 in 4 chunks of 64) stream through a 3-stage cp.async ring.
// Stage: Ahi 16K | Alo 16K | Bhi 32K = 64KB; 3 stages = 192KB.
// =============================================================================
#define STAGE_B 65536
#define GEMM_SMEM (3 * STAGE_B)

__global__ __launch_bounds__(256, 1) void gemm_mma_kernel()
{
    extern __shared__ char sm[];
    const uint32_t sb = smem_u32(sm);
    __shared__ float sd[64], sd2[64];

    const int tid  = threadIdx.x;
    const int warp = tid >> 5;
    const int lane = tid & 31;
    const int wm   = (warp >> 2) * 64;
    const int wn   = (warp & 3) * 64;

    const int blk  = blockIdx.x;
    const int p    = blk & 1;              // parity: which&1
    const int row0 = (blk >> 1) * 128;
    const int jb   = p ? 1024 : 0;

    const __half* __restrict__ Xhi = g_Xhi + (size_t)p * NXF;
    const __half* __restrict__ Xlo = g_Xlo + (size_t)p * NXF;

    if (tid < 64) { sd[tid] = 0.f; sd2[tid] = 0.f; }

    float acc[4][8][4];
    #pragma unroll
    for (int a = 0; a < 4; a++)
        #pragma unroll
        for (int b = 0; b < 8; b++)
            #pragma unroll
            for (int c = 0; c < 4; c++) acc[a][b][c] = 0.f;

    const int lr = tid >> 1;            // 0..127
    const int cb = (tid & 1) * 4;       // 16B-chunk base within 128B row

    // issue chunk g into stage st
    auto issue = [&](int g, int st) {
        const int tile  = g >> 2;
        const int kc    = g & 3;
        const int which = p + 2 * (tile >> 2);
        const int col0  = (tile & 3) * 256;
        uint32_t stg = sb + st * STAGE_B;
        // A hi/lo: row lr
        {
            const __half* s0 = Xhi + (size_t)(row0 + lr) * 256 + kc * 64 + cb * 8;
            const __half* s1 = Xlo + (size_t)(row0 + lr) * 256 + kc * 64 + cb * 8;
            uint32_t d0 = stg + lr * 128;
            #pragma unroll
            for (int q = 0; q < 4; q++) {
                uint32_t sw = ((cb + q) ^ (lr & 7)) << 4;
                CP16(d0 + sw,         s0 + q * 8);
                CP16(d0 + 16384 + sw, s1 + q * 8);
            }
        }
        // B hi: rows lr and lr+128
        const __half* Wb = g_Whi + (size_t)which * NWF;
        #pragma unroll
        for (int hh = 0; hh < 2; hh++) {
            int r = lr + hh * 128;
            const __half* s0 = Wb + (size_t)(col0 + r) * 256 + kc * 64 + cb * 8;
            uint32_t d0 = stg + 32768 + r * 128;
            #pragma unroll
            for (int q = 0; q < 4; q++) {
                uint32_t sw = ((cb + q) ^ (r & 7)) << 4;
                CP16(d0 + sw, s0 + q * 8);
            }
        }
    };

    issue(0, 0); CP_COMMIT();
    issue(1, 1); CP_COMMIT();

    const int rlo   = lane >> 2;
    const int cpair = (lane & 3) * 2;

    for (int g = 0; g < 32; g++) {
        if (g < 31) { CP_WAIT1(); } else { CP_WAIT0(); }
        __syncthreads();
        if (g + 2 < 32) { issue(g + 2, (g + 2) % 3); CP_COMMIT(); }

        const uint32_t stg = sb + (g % 3) * STAGE_B;
        #pragma unroll
        for (int k16 = 0; k16 < 4; k16++) {
            uint32_t ah[4][4], al[4][4];
            #pragma unroll
            for (int mf = 0; mf < 4; mf++) {
                int r = wm + mf * 16 + (lane & 15);
                int ch = 2 * k16 + (lane >> 4);
                uint32_t ad = stg + r * 128 + ((ch ^ (r & 7)) << 4);
                LDSM4(ah[mf][0], ah[mf][1], ah[mf][2], ah[mf][3], ad);
                LDSM4(al[mf][0], al[mf][1], al[mf][2], al[mf][3], ad + 16384);
            }
            #pragma unroll
            for (int j = 0; j < 4; j++) {
                int r = wn + j * 16 + (lane & 15);
                int ch = 2 * k16 + (lane >> 4);
                uint32_t bd = stg + 32768 + r * 128 + ((ch ^ (r & 7)) << 4);
                uint32_t b0, b1, b2, b3;
                LDSM4(b0, b1, b2, b3, bd);
                #pragma unroll
                for (int mf = 0; mf < 4; mf++) {
                    MMA16816(acc[mf][2 * j],     ah[mf], b0, b2);
                    MMA16816(acc[mf][2 * j + 1], ah[mf], b1, b3);
                    MMA16816(acc[mf][2 * j],     al[mf], b0, b2);
                    MMA16816(acc[mf][2 * j + 1], al[mf], b1, b3);
                }
            }
        }

        if ((g & 3) == 3) {
            // -------- tile epilogue: store + (K tiles) stats ------------------
            const int tile  = g >> 2;
            const int which = p + 2 * (tile >> 2);
            const int col0  = (tile & 3) * 256;
            float* C = (which < 2) ? g_K : g_V;
            #pragma unroll
            for (int mf = 0; mf < 4; mf++) {
                #pragma unroll
                for (int nf = 0; nf < 8; nf++) {
                    int row = row0 + wm + mf * 16 + rlo;
                    int col = jb + col0 + wn + nf * 8 + cpair;
                    *(float2*)(C + (size_t)row * 2048 + col) =
                        make_float2(acc[mf][nf][0], acc[mf][nf][1]);
                    *(float2*)(C + (size_t)(row + 8) * 2048 + col) =
                        make_float2(acc[mf][nf][2], acc[mf][nf][3]);
                }
            }
            if (which < 2) {
                #pragma unroll
                for (int nf = 0; nf < 8; nf++) {
                    float s0 = 0.f, s1 = 0.f, q0 = 0.f, q1 = 0.f;
                    #pragma unroll
                    for (int mf = 0; mf < 4; mf++) {
                        float a0 = acc[mf][nf][0], a1 = acc[mf][nf][1];
                        float a2 = acc[mf][nf][2], a3 = acc[mf][nf][3];
                        s0 += a0 + a2;  s1 += a1 + a3;
                        q0 += a0 * a0 + a2 * a2;
                        q1 += a1 * a1 + a3 * a3;
                    }
                    #pragma unroll
                    for (int o = 4; o <= 16; o <<= 1) {
                        s0 += __shfl_xor_sync(0xffffffffu, s0, o);
                        s1 += __shfl_xor_sync(0xffffffffu, s1, o);
                        q0 += __shfl_xor_sync(0xffffffffu, q0, o);
                        q1 += __shfl_xor_sync(0xffffffffu, q1, o);
                    }
                    if (lane < 4) {
                        int d = (wn + nf * 8 + lane * 2) & 63;
                        atomicAdd(&sd[d], s0);   atomicAdd(&sd[d + 1], s1);
                        atomicAdd(&sd2[d], q0);  atomicAdd(&sd2[d + 1], q1);
                    }
                }
            }
            #pragma unroll
            for (int a = 0; a < 4; a++)
                #pragma unroll
                for (int b = 0; b < 8; b++)
                    #pragma unroll
                    for (int c2 = 0; c2 < 4; c2++) acc[a][b][c2] = 0.f;
        }
    }

    __syncthreads();
    if (tid < 64) {
        atomicAdd(&g_sumK[tid], sd[tid]);
        atomicAdd(&g_sumK2[tid], sd2[tid]);
    }
}

// ---------------- fold BN stats into per-d affine constants ------------------
__global__ void finalize_kernel(const float* __restrict__ Wq,
                                const float* __restrict__ gammaQ,
                                const float* __restrict__ betaQ,
                                const float* __restrict__ gammaK,
                                const float* __restrict__ betaK)
{
    int d = threadIdx.x;
    if (d >= 64) return;
    const float invB = 1.f / 65536.f;

    float w[4];
    #pragma unroll
    for (int c = 0; c < 4; c++) w[c] = Wq[d * 4 + c];

    float mQ = 0.f;
    #pragma unroll
    for (int c = 0; c < 4; c++) mQ += (g_cmd[c] * invB) * w[c];
    float eq2 = 0.f;
    #pragma unroll
    for (int c1 = 0; c1 < 4; c1++)
        #pragma unroll
        for (int c2 = 0; c2 < 4; c2++)
            eq2 += w[c1] * w[c2] * g_cmd[4 + c1 * 4 + c2];
    eq2 *= invB;
    float vQ = eq2 - mQ * mQ;
    float gq = gammaQ[d] / sqrtf(vQ + EPS);
    g_cst[d]      = gq;
    g_cst[64 + d] = betaQ[d] - mQ * gq;

    const float invBF = 1.f / (65536.f * 32.f);
    float mK = g_sumK[d] * invBF;
    float vK = g_sumK2[d] * invBF - mK * mK;
    float aK = gammaK[d] / sqrtf(vK + EPS);
    g_cst[128 + d] = aK;
    g_cst[192 + d] = betaK[d] - mK * aK;
}

// ---------------- attention: 1 warp per batch row -----------------------------
__global__ __launch_bounds__(256) void attn_kernel(
    const float* __restrict__ command, const float* __restrict__ Wq,
    float* __restrict__ out)
{
    __shared__ float sh_qa[8][64];
    const int w    = threadIdx.x >> 5;
    const int lane = threadIdx.x & 31;
    const int b    = blockIdx.x * 8 + w;

    float4 c4 = *(const float4*)(command + (size_t)b * 4);
    const int d0 = lane, d1 = lane + 32;

    float q0 = c4.x * Wq[d0 * 4 + 0] + c4.y * Wq[d0 * 4 + 1] +
               c4.z * Wq[d0 * 4 + 2] + c4.w * Wq[d0 * 4 + 3];
    float q1 = c4.x * Wq[d1 * 4 + 0] + c4.y * Wq[d1 * 4 + 1] +
               c4.z * Wq[d1 * 4 + 2] + c4.w * Wq[d1 * 4 + 3];
    float qn0 = q0 * g_cst[d0] + g_cst[64 + d0];
    float qn1 = q1 * g_cst[d1] + g_cst[64 + d1];

    float qa0 = qn0 * g_cst[128 + d0];
    float qa1 = qn1 * g_cst[128 + d1];
    float qc  = qn0 * g_cst[192 + d0] + qn1 * g_cst[192 + d1];
    #pragma unroll
    for (int o = 16; o; o >>= 1) qc += __shfl_xor_sync(0xffffffffu, qc, o);

    sh_qa[w][d0] = qa0;
    sh_qa[w][d1] = qa1;
    __syncwarp();

    const float4* Kr = (const float4*)(g_K + (size_t)b * 2048 + lane * 64);
    float acc = 0.f;
    #pragma unroll
    for (int t = 0; t < 16; t++) {
        float4 k4 = Kr[t];
        acc += sh_qa[w][4 * t + 0] * k4.x + sh_qa[w][4 * t + 1] * k4.y +
               sh_qa[w][4 * t + 2] * k4.z + sh_qa[w][4 * t + 3] * k4.w;
    }
    float logit = (acc + qc) * 0.125f;

    float mx = logit;
    #pragma unroll
    for (int o = 16; o; o >>= 1) mx = fmaxf(mx, __shfl_xor_sync(0xffffffffu, mx, o));
    float e = __expf(logit - mx);
    float den = e;
    #pragma unroll
    for (int o = 16; o; o >>= 1) den += __shfl_xor_sync(0xffffffffu, den, o);
    float a = e / den;

    const float* Vr = g_V + (size_t)b * 2048;
    float s0 = 0.f, s1 = 0.f;
    #pragma unroll
    for (int f = 0; f < 32; f++) {
        float af = __shfl_sync(0xffffffffu, a, f);
        s0 += af * Vr[f * 64 + d0];
        s1 += af * Vr[f * 64 + d1];
    }
    out[(size_t)b * 64 + d0] = s0;
    out[(size_t)b * 64 + d1] = s1;
}

// ---------------- launch ------------------------------------------------------
extern "C" void kernel_launch(void* const* d_in, const int* in_sizes, int n_in,
                              void* d_out, int out_size)
{
    const float* feature = (const float*)d_in[0];
    const float* hidden  = (const float*)d_in[1];
    const float* command = (const float*)d_in[2];
    const float* Wq      = (const float*)d_in[3];
    const float* Wkz     = (const float*)d_in[4];
    const float* Wkh     = (const float*)d_in[5];
    const float* Wvz     = (const float*)d_in[6];
    const float* Wvh     = (const float*)d_in[7];
    const float* gammaQ  = (const float*)d_in[8];
    const float* betaQ   = (const float*)d_in[9];
    const float* gammaK  = (const float*)d_in[10];
    const float* betaK   = (const float*)d_in[11];
    float* out = (float*)d_out;

    cudaFuncSetAttribute(gemm_mma_kernel,
                         cudaFuncAttributeMaxDynamicSharedMemorySize, GEMM_SMEM);

    zero_stats_kernel<<<1, 64>>>();
    cmd_stats_kernel<<<128, 256>>>(command);
    split_kernel<<<33792, 256>>>(feature, hidden, Wkz, Wkh, Wvz, Wvh);
    gemm_mma_kernel<<<1024, 256, GEMM_SMEM>>>();
    finalize_kernel<<<1, 64>>>(Wq, gammaQ, betaQ, gammaK, betaK);
    attn_kernel<<<B_TOT / 8, 256>>>(command, Wq, out);
}

// round 5
// speedup vs baseline: 2.6321x; 1.0191x over previous
#include <cuda_runtime.h>
#include <cuda_fp16.h>
#include <cstdint>
#include <math.h>

#define B_TOT 65536
#define EPS 1e-5f
#define NXF (65536 * 256)          // floats per X plane
#define NWF (1024 * 256)           // floats per W plane

// ---------------- scratch (static device globals; no runtime alloc) ----------
__device__ float g_K[(size_t)B_TOT * 2048];            // 512 MB
__device__ float g_V[(size_t)B_TOT * 2048];            // 512 MB
__device__ __half g_Xhi[(size_t)2 * NXF];              // 64 MB
__device__ __half g_Xlo[(size_t)2 * NXF];              // 64 MB
__device__ __half g_Whi[(size_t)4 * NWF];              // 2 MB
__device__ float g_sumK[64];
__device__ float g_sumK2[64];
__device__ float g_cmd[20];
__device__ float g_cst[256];

// ================= PTX helpers (sm_80-era; safe on plain sm_103) =============
__device__ __forceinline__ uint32_t smem_u32(const void* p) {
    uint32_t a;
    asm("{ .reg .u64 t; cvta.to.shared.u64 t, %1; cvt.u32.u64 %0, t; }" : "=r"(a) : "l"(p));
    return a;
}
#define CP16(dst, src) \
    asm volatile("cp.async.cg.shared.global [%0], [%1], 16;" :: "r"(dst), "l"(src))
#define CP_COMMIT() asm volatile("cp.async.commit_group;")
#define CP_WAIT1()  asm volatile("cp.async.wait_group 1;")
#define CP_WAIT0()  asm volatile("cp.async.wait_group 0;")

#define LDSM4(r0, r1, r2, r3, addr) \
    asm volatile("ldmatrix.sync.aligned.m8n8.x4.shared.b16 {%0,%1,%2,%3}, [%4];" \
                 : "=r"(r0), "=r"(r1), "=r"(r2), "=r"(r3) : "r"(addr))

#define MMA16816(d, a, b0, b1) \
    asm volatile("mma.sync.aligned.m16n8k16.row.col.f32.f16.f16.f32 " \
                 "{%0,%1,%2,%3},{%4,%5,%6,%7},{%8,%9},{%0,%1,%2,%3};" \
                 : "+f"((d)[0]), "+f"((d)[1]), "+f"((d)[2]), "+f"((d)[3]) \
                 : "r"((a)[0]), "r"((a)[1]), "r"((a)[2]), "r"((a)[3]), \
                   "r"(b0), "r"(b1))

// ---------------- zero the accumulators --------------------------------------
__global__ void zero_stats_kernel() {
    int t = threadIdx.x;
    if (t < 64) { g_sumK[t] = 0.f; g_sumK2[t] = 0.f; }
    if (t < 20) { g_cmd[t] = 0.f; }
}

// ---------------- command column sums + 4x4 Gram ------------------------------
__global__ void cmd_stats_kernel(const float* __restrict__ command) {
    float s[4]  = {0.f, 0.f, 0.f, 0.f};
    float g[16] = {0.f};
    int stride = gridDim.x * blockDim.x;
    for (int b = blockIdx.x * blockDim.x + threadIdx.x; b < B_TOT; b += stride) {
        float4 c = *(const float4*)(command + (size_t)b * 4);
        float v[4] = {c.x, c.y, c.z, c.w};
        #pragma unroll
        for (int i = 0; i < 4; i++) {
            s[i] += v[i];
            #pragma unroll
            for (int j = 0; j < 4; j++) g[i * 4 + j] += v[i] * v[j];
        }
    }
    __shared__ float sh[20];
    if (threadIdx.x < 20) sh[threadIdx.x] = 0.f;
    __syncthreads();
    #pragma unroll
    for (int i = 0; i < 4; i++) atomicAdd(&sh[i], s[i]);
    #pragma unroll
    for (int i = 0; i < 16; i++) atomicAdd(&sh[4 + i], g[i]);
    __syncthreads();
    if (threadIdx.x < 20) atomicAdd(&g_cmd[threadIdx.x], sh[threadIdx.x]);
}

// ---------------- split: X -> fp16 hi+lo planes, W -> fp16 hi -----------------
__global__ __launch_bounds__(256) void split_kernel(
    const float* __restrict__ f, const float* __restrict__ h,
    const float* __restrict__ wkz, const float* __restrict__ wkh,
    const float* __restrict__ wvz, const float* __restrict__ wvh)
{
    const size_t NX4 = (size_t)2 * NXF / 4;
    size_t gid = (size_t)blockIdx.x * 256 + threadIdx.x;

    if (gid < NX4) {
        size_t base = gid * 4;
        const float* src = (base < (size_t)NXF) ? (f + base) : (h + (base - NXF));
        float4 v = *(const float4*)src;
        float vv[4] = {v.x, v.y, v.z, v.w};
        ushort4 uh, ul;
        unsigned short* ph = (unsigned short*)&uh;
        unsigned short* pl = (unsigned short*)&ul;
        #pragma unroll
        for (int i = 0; i < 4; i++) {
            __half hi = __float2half_rn(vv[i]);
            __half lo = __float2half_rn(vv[i] - __half2float(hi));
            ph[i] = __half_as_ushort(hi);
            pl[i] = __half_as_ushort(lo);
        }
        *(ushort4*)(g_Xhi + base) = uh;
        *(ushort4*)(g_Xlo + base) = ul;
    } else {
        size_t base = (gid - NX4) * 4;
        size_t o = base;
        const float* src;
        if      (o < (size_t)NWF)       src = wkz + o;
        else if (o < (size_t)2 * NWF)   src = wkh + (o - NWF);
        else if (o < (size_t)3 * NWF)   src = wvz + (o - 2 * (size_t)NWF);
        else                            src = wvh + (o - 3 * (size_t)NWF);
        float4 v = *(const float4*)src;
        float vv[4] = {v.x, v.y, v.z, v.w};
        ushort4 uh;
        unsigned short* ph = (unsigned short*)&uh;
        #pragma unroll
        for (int i = 0; i < 4; i++)
            ph[i] = __half_as_ushort(__float2half_rn(vv[i]));
        *(ushort4*)(g_Whi + base) = uh;
    }
}

// =============================================================================
// HMMA fp16 2-term GEMM, block-persistent, A-resident.
// 1024 CTAs x 512 threads (16 warps). CTA b: row0=(b>>1)*128, parity p=b&1.
// A (128 x 256, hi+lo fp16) loaded ONCE into smem (128KB).
// 8 tiles of 128x256: which in {p,p+2} x 4 col-tiles; 32 chunks of K=64 stream
// B through a 3-stage 32KB cp.async ring.  Warp tile 32x64.
// smem: A 131072 | B 3*32768 = 229376 bytes.
// =============================================================================
#define A_BYTES  131072
#define BSTG_B   32768
#define GEMM_SMEM (A_BYTES + 3 * BSTG_B)

__global__ __launch_bounds__(512, 1) void gemm_mma_kernel()
{
    extern __shared__ char sm[];
    const uint32_t sb = smem_u32(sm);
    __shared__ float sd[64], sd2[64];

    const int tid  = threadIdx.x;
    const int warp = tid >> 5;
    const int lane = tid & 31;
    const int wm   = (warp >> 2) * 32;     // warp M origin 0..96
    const int wn   = (warp & 3) * 64;      // warp N origin 0..192

    const int blk  = blockIdx.x;
    const int p    = blk & 1;
    const int row0 = (blk >> 1) * 128;
    const int jb   = p ? 1024 : 0;

    const __half* __restrict__ Xhi = g_Xhi + (size_t)p * NXF;
    const __half* __restrict__ Xlo = g_Xlo + (size_t)p * NXF;

    if (tid < 64) { sd[tid] = 0.f; sd2[tid] = 0.f; }

    float acc[2][8][4];
    #pragma unroll
    for (int a = 0; a < 2; a++)
        #pragma unroll
        for (int b = 0; b < 8; b++)
            #pragma unroll
            for (int c = 0; c < 4; c++) acc[a][b][c] = 0.f;

    // ---- A resident load: thread -> row r=tid>>2, chunks (tid&3)*8 .. +7 -----
    {
        const int r   = tid >> 2;
        const int cb0 = (tid & 3) * 8;
        const __half* s0 = Xhi + (size_t)(row0 + r) * 256;
        const __half* s1 = Xlo + (size_t)(row0 + r) * 256;
        const uint32_t rb = sb + r * 512;
        #pragma unroll
        for (int q = 0; q < 8; q++) {
            int ch = cb0 + q;
            uint32_t sw = (uint32_t)((ch & 24) | ((ch ^ (r & 7)) & 7)) << 4;
            CP16(rb + sw,          s0 + ch * 8);
            CP16(rb + 65536 + sw,  s1 + ch * 8);
        }
    }

    // ---- B chunk issue ---------------------------------------------------------
    const int lr = tid >> 1;            // 0..255
    const int cb = (tid & 1) * 4;
    auto issueB = [&](int g, int st) {
        const int tile  = g >> 2;
        const int kc    = g & 3;
        const int which = p + 2 * (tile >> 2);
        const int col0  = (tile & 3) * 256;
        const __half* Wb = g_Whi + (size_t)which * NWF +
                           (size_t)(col0 + lr) * 256 + kc * 64 + cb * 8;
        uint32_t d0 = sb + A_BYTES + st * BSTG_B + lr * 128;
        #pragma unroll
        for (int q = 0; q < 4; q++) {
            uint32_t sw = (uint32_t)((cb + q) ^ (lr & 7)) << 4;
            CP16(d0 + sw, Wb + q * 8);
        }
    };

    issueB(0, 0); CP_COMMIT();   // group0 = A + B0
    issueB(1, 1); CP_COMMIT();

    const int rlo   = lane >> 2;
    const int cpair = (lane & 3) * 2;
    const int lrow  = lane & 15;
    const int lhalf = lane >> 4;

    for (int g = 0; g < 32; g++) {
        if (g < 31) { CP_WAIT1(); } else { CP_WAIT0(); }
        __syncthreads();
        if (g + 2 < 32) { issueB(g + 2, (g + 2) % 3); CP_COMMIT(); }

        const int kc = g & 3;
        const uint32_t bstg = sb + A_BYTES + (g % 3) * BSTG_B;

        #pragma unroll
        for (int k16 = 0; k16 < 4; k16++) {
            uint32_t ah[2][4], al[2][4];
            #pragma unroll
            for (int mf = 0; mf < 2; mf++) {
                int r  = wm + mf * 16 + lrow;
                int ch = kc * 8 + 2 * k16 + lhalf;
                uint32_t sw = (uint32_t)((ch & 24) | ((ch ^ (r & 7)) & 7)) << 4;
                uint32_t ad = sb + r * 512 + sw;
                LDSM4(ah[mf][0], ah[mf][1], ah[mf][2], ah[mf][3], ad);
                LDSM4(al[mf][0], al[mf][1], al[mf][2], al[mf][3], ad + 65536);
            }
            #pragma unroll
            for (int j = 0; j < 4; j++) {
                int r  = wn + j * 16 + lrow;
                int ch = 2 * k16 + lhalf;
                uint32_t bd = bstg + r * 128 + ((uint32_t)((ch ^ (r & 7)) & 7) << 4);
                uint32_t b0, b1, b2, b3;
                LDSM4(b0, b1, b2, b3, bd);
                #pragma unroll
                for (int mf = 0; mf < 2; mf++) {
                    MMA16816(acc[mf][2 * j],     ah[mf], b0, b2);
                    MMA16816(acc[mf][2 * j + 1], ah[mf], b1, b3);
                    MMA16816(acc[mf][2 * j],     al[mf], b0, b2);
                    MMA16816(acc[mf][2 * j + 1], al[mf], b1, b3);
                }
            }
        }

        if ((g & 3) == 3) {
            // -------- tile epilogue: store + (K tiles) stats ------------------
            const int tile  = g >> 2;
            const int which = p + 2 * (tile >> 2);
            const int col0  = (tile & 3) * 256;
            float* C = (which < 2) ? g_K : g_V;
            #pragma unroll
            for (int mf = 0; mf < 2; mf++) {
                #pragma unroll
                for (int nf = 0; nf < 8; nf++) {
                    int row = row0 + wm + mf * 16 + rlo;
                    int col = jb + col0 + wn + nf * 8 + cpair;
                    *(float2*)(C + (size_t)row * 2048 + col) =
                        make_float2(acc[mf][nf][0], acc[mf][nf][1]);
                    *(float2*)(C + (size_t)(row + 8) * 2048 + col) =
                        make_float2(acc[mf][nf][2], acc[mf][nf][3]);
                }
            }
            if (which < 2) {
                #pragma unroll
                for (int nf = 0; nf < 8; nf++) {
                    float s0 = 0.f, s1 = 0.f, q0 = 0.f, q1 = 0.f;
                    #pragma unroll
                    for (int mf = 0; mf < 2; mf++) {
                        float a0 = acc[mf][nf][0], a1 = acc[mf][nf][1];
                        float a2 = acc[mf][nf][2], a3 = acc[mf][nf][3];
                        s0 += a0 + a2;  s1 += a1 + a3;
                        q0 += a0 * a0 + a2 * a2;
                        q1 += a1 * a1 + a3 * a3;
                    }
                    #pragma unroll
                    for (int o = 4; o <= 16; o <<= 1) {
                        s0 += __shfl_xor_sync(0xffffffffu, s0, o);
                        s1 += __shfl_xor_sync(0xffffffffu, s1, o);
                        q0 += __shfl_xor_sync(0xffffffffu, q0, o);
                        q1 += __shfl_xor_sync(0xffffffffu, q1, o);
                    }
                    if (lane < 4) {
                        int d = (wn + nf * 8 + lane * 2) & 63;
                        atomicAdd(&sd[d], s0);   atomicAdd(&sd[d + 1], s1);
                        atomicAdd(&sd2[d], q0);  atomicAdd(&sd2[d + 1], q1);
                    }
                }
            }
            #pragma unroll
            for (int a = 0; a < 2; a++)
                #pragma unroll
                for (int b = 0; b < 8; b++)
                    #pragma unroll
                    for (int c2 = 0; c2 < 4; c2++) acc[a][b][c2] = 0.f;
        }
    }

    __syncthreads();
    if (tid < 64) {
        atomicAdd(&g_sumK[tid], sd[tid]);
        atomicAdd(&g_sumK2[tid], sd2[tid]);
    }
}

// ---------------- fold BN stats into per-d affine constants ------------------
__global__ void finalize_kernel(const float* __restrict__ Wq,
                                const float* __restrict__ gammaQ,
                                const float* __restrict__ betaQ,
                                const float* __restrict__ gammaK,
                                const float* __restrict__ betaK)
{
    int d = threadIdx.x;
    if (d >= 64) return;
    const float invB = 1.f / 65536.f;

    float w[4];
    #pragma unroll
    for (int c = 0; c < 4; c++) w[c] = Wq[d * 4 + c];

    float mQ = 0.f;
    #pragma unroll
    for (int c = 0; c < 4; c++) mQ += (g_cmd[c] * invB) * w[c];
    float eq2 = 0.f;
    #pragma unroll
    for (int c1 = 0; c1 < 4; c1++)
        #pragma unroll
        for (int c2 = 0; c2 < 4; c2++)
            eq2 += w[c1] * w[c2] * g_cmd[4 + c1 * 4 + c2];
    eq2 *= invB;
    float vQ = eq2 - mQ * mQ;
    float gq = gammaQ[d] / sqrtf(vQ + EPS);
    g_cst[d]      = gq;
    g_cst[64 + d] = betaQ[d] - mQ * gq;

    const float invBF = 1.f / (65536.f * 32.f);
    float mK = g_sumK[d] * invBF;
    float vK = g_sumK2[d] * invBF - mK * mK;
    float aK = gammaK[d] / sqrtf(vK + EPS);
    g_cst[128 + d] = aK;
    g_cst[192 + d] = betaK[d] - mK * aK;
}

// ---------------- attention: 1 warp per batch row -----------------------------
__global__ __launch_bounds__(256) void attn_kernel(
    const float* __restrict__ command, const float* __restrict__ Wq,
    float* __restrict__ out)
{
    __shared__ float sh_qa[8][64];
    const int w    = threadIdx.x >> 5;
    const int lane = threadIdx.x & 31;
    const int b    = blockIdx.x * 8 + w;

    float4 c4 = *(const float4*)(command + (size_t)b * 4);
    const int d0 = lane, d1 = lane + 32;

    float q0 = c4.x * Wq[d0 * 4 + 0] + c4.y * Wq[d0 * 4 + 1] +
               c4.z * Wq[d0 * 4 + 2] + c4.w * Wq[d0 * 4 + 3];
    float q1 = c4.x * Wq[d1 * 4 + 0] + c4.y * Wq[d1 * 4 + 1] +
               c4.z * Wq[d1 * 4 + 2] + c4.w * Wq[d1 * 4 + 3];
    float qn0 = q0 * g_cst[d0] + g_cst[64 + d0];
    float qn1 = q1 * g_cst[d1] + g_cst[64 + d1];

    float qa0 = qn0 * g_cst[128 + d0];
    float qa1 = qn1 * g_cst[128 + d1];
    float qc  = qn0 * g_cst[192 + d0] + qn1 * g_cst[192 + d1];
    #pragma unroll
    for (int o = 16; o; o >>= 1) qc += __shfl_xor_sync(0xffffffffu, qc, o);

    sh_qa[w][d0] = qa0;
    sh_qa[w][d1] = qa1;
    __syncwarp();

    const float4* Kr = (const float4*)(g_K + (size_t)b * 2048 + lane * 64);
    float acc = 0.f;
    #pragma unroll
    for (int t = 0; t < 16; t++) {
        float4 k4 = Kr[t];
        acc += sh_qa[w][4 * t + 0] * k4.x + sh_qa[w][4 * t + 1] * k4.y +
               sh_qa[w][4 * t + 2] * k4.z + sh_qa[w][4 * t + 3] * k4.w;
    }
    float logit = (acc + qc) * 0.125f;

    float mx = logit;
    #pragma unroll
    for (int o = 16; o; o >>= 1) mx = fmaxf(mx, __shfl_xor_sync(0xffffffffu, mx, o));
    float e = __expf(logit - mx);
    float den = e;
    #pragma unroll
    for (int o = 16; o; o >>= 1) den += __shfl_xor_sync(0xffffffffu, den, o);
    float a = e / den;

    const float* Vr = g_V + (size_t)b * 2048;
    float s0 = 0.f, s1 = 0.f;
    #pragma unroll
    for (int f = 0; f < 32; f++) {
        float af = __shfl_sync(0xffffffffu, a, f);
        s0 += af * Vr[f * 64 + d0];
        s1 += af * Vr[f * 64 + d1];
    }
    out[(size_t)b * 64 + d0] = s0;
    out[(size_t)b * 64 + d1] = s1;
}

// ---------------- launch ------------------------------------------------------
extern "C" void kernel_launch(void* const* d_in, const int* in_sizes, int n_in,
                              void* d_out, int out_size)
{
    const float* feature = (const float*)d_in[0];
    const float* hidden  = (const float*)d_in[1];
    const float* command = (const float*)d_in[2];
    const float* Wq      = (const float*)d_in[3];
    const float* Wkz     = (const float*)d_in[4];
    const float* Wkh     = (const float*)d_in[5];
    const float* Wvz     = (const float*)d_in[6];
    const float* Wvh     = (const float*)d_in[7];
    const float* gammaQ  = (const float*)d_in[8];
    const float* betaQ   = (const float*)d_in[9];
    const float* gammaK  = (const float*)d_in[10];
    const float* betaK   = (const float*)d_in[11];
    float* out = (float*)d_out;

    cudaFuncSetAttribute(gemm_mma_kernel,
                         cudaFuncAttributeMaxDynamicSharedMemorySize, GEMM_SMEM);

    zero_stats_kernel<<<1, 64>>>();
    cmd_stats_kernel<<<128, 256>>>(command);
    split_kernel<<<33792, 256>>>(feature, hidden, Wkz, Wkh, Wvz, Wvh);
    gemm_mma_kernel<<<1024, 512, GEMM_SMEM>>>();
    finalize_kernel<<<1, 64>>>(Wq, gammaQ, betaQ, gammaK, betaK);
    attn_kernel<<<B_TOT / 8, 256>>>(command, Wq, out);
}

// round 6
// speedup vs baseline: 3.4607x; 1.3148x over previous
#include <cuda_runtime.h>
#include <cuda_fp16.h>
#include <cstdint>
#include <math.h>

#define B_TOT 65536
#define EPS 1e-5f
#define NXF (65536 * 256)          // floats per X plane
#define NWF (1024 * 256)           // floats per W plane

// ---------------- scratch (static device globals; no runtime alloc) ----------
__device__ __half g_Kh[(size_t)B_TOT * 2048];          // 256 MB (fp16 K)
__device__ float  g_V [(size_t)B_TOT * 2048];          // 512 MB
__device__ __half g_Xh[(size_t)2 * NXF];               // 64 MB (fp16 X)
__device__ __half g_Wh[(size_t)4 * NWF];               // 2 MB (fp16 W)
__device__ float g_sumK[64];
__device__ float g_sumK2[64];
__device__ float g_cmd[20];
__device__ float g_cst[256];

// ================= PTX helpers (sm_80-era; safe on plain sm_103) =============
__device__ __forceinline__ uint32_t smem_u32(const void* p) {
    uint32_t a;
    asm("{ .reg .u64 t; cvta.to.shared.u64 t, %1; cvt.u32.u64 %0, t; }" : "=r"(a) : "l"(p));
    return a;
}
#define CP16(dst, src) \
    asm volatile("cp.async.cg.shared.global [%0], [%1], 16;" :: "r"(dst), "l"(src))
#define CP_COMMIT() asm volatile("cp.async.commit_group;")
#define CP_WAIT3()  asm volatile("cp.async.wait_group 3;")
#define CP_WAIT0()  asm volatile("cp.async.wait_group 0;")

#define LDSM4(r0, r1, r2, r3, addr) \
    asm volatile("ldmatrix.sync.aligned.m8n8.x4.shared.b16 {%0,%1,%2,%3}, [%4];" \
                 : "=r"(r0), "=r"(r1), "=r"(r2), "=r"(r3) : "r"(addr))

#define MMA16816(d, a, b0, b1) \
    asm volatile("mma.sync.aligned.m16n8k16.row.col.f32.f16.f16.f32 " \
                 "{%0,%1,%2,%3},{%4,%5,%6,%7},{%8,%9},{%0,%1,%2,%3};" \
                 : "+f"((d)[0]), "+f"((d)[1]), "+f"((d)[2]), "+f"((d)[3]) \
                 : "r"((a)[0]), "r"((a)[1]), "r"((a)[2]), "r"((a)[3]), \
                   "r"(b0), "r"(b1))

// ---------------- zero the accumulators --------------------------------------
__global__ void zero_stats_kernel() {
    int t = threadIdx.x;
    if (t < 64) { g_sumK[t] = 0.f; g_sumK2[t] = 0.f; }
    if (t < 20) { g_cmd[t] = 0.f; }
}

// ---------------- command column sums + 4x4 Gram ------------------------------
__global__ void cmd_stats_kernel(const float* __restrict__ command) {
    float s[4]  = {0.f, 0.f, 0.f, 0.f};
    float g[16] = {0.f};
    int stride = gridDim.x * blockDim.x;
    for (int b = blockIdx.x * blockDim.x + threadIdx.x; b < B_TOT; b += stride) {
        float4 c = *(const float4*)(command + (size_t)b * 4);
        float v[4] = {c.x, c.y, c.z, c.w};
        #pragma unroll
        for (int i = 0; i < 4; i++) {
            s[i] += v[i];
            #pragma unroll
            for (int j = 0; j < 4; j++) g[i * 4 + j] += v[i] * v[j];
        }
    }
    __shared__ float sh[20];
    if (threadIdx.x < 20) sh[threadIdx.x] = 0.f;
    __syncthreads();
    #pragma unroll
    for (int i = 0; i < 4; i++) atomicAdd(&sh[i], s[i]);
    #pragma unroll
    for (int i = 0; i < 16; i++) atomicAdd(&sh[4 + i], g[i]);
    __syncthreads();
    if (threadIdx.x < 20) atomicAdd(&g_cmd[threadIdx.x], sh[threadIdx.x]);
}

// ---------------- convert X and W to fp16 -------------------------------------
__global__ __launch_bounds__(256) void split_kernel(
    const float* __restrict__ f, const float* __restrict__ h,
    const float* __restrict__ wkz, const float* __restrict__ wkh,
    const float* __restrict__ wvz, const float* __restrict__ wvh)
{
    const size_t NX4 = (size_t)2 * NXF / 4;
    size_t gid = (size_t)blockIdx.x * 256 + threadIdx.x;

    const float* src;
    __half* dst;
    size_t base;
    if (gid < NX4) {
        base = gid * 4;
        src = (base < (size_t)NXF) ? (f + base) : (h + (base - NXF));
        dst = g_Xh + base;
    } else {
        base = (gid - NX4) * 4;
        size_t o = base;
        if      (o < (size_t)NWF)       src = wkz + o;
        else if (o < (size_t)2 * NWF)   src = wkh + (o - NWF);
        else if (o < (size_t)3 * NWF)   src = wvz + (o - 2 * (size_t)NWF);
        else                            src = wvh + (o - 3 * (size_t)NWF);
        dst = g_Wh + base;
    }
    float4 v = *(const float4*)src;
    float vv[4] = {v.x, v.y, v.z, v.w};
    ushort4 uh;
    unsigned short* ph = (unsigned short*)&uh;
    #pragma unroll
    for (int i = 0; i < 4; i++)
        ph[i] = __half_as_ushort(__float2half_rn(vv[i]));
    *(ushort4*)dst = uh;
}

// =============================================================================
// HMMA fp16 single-term GEMM, block-persistent, A-resident.
// 1024 CTAs x 512 threads (16 warps). CTA b: row0=(b>>1)*128, parity p=b&1.
// A (128 x 256 fp16) loaded ONCE into smem (64KB).
// 8 tiles of 128x256: which in {p,p+2} x 4 col-tiles; 32 chunks of K=64 stream
// B through a 5-stage 32KB cp.async ring.  Warp tile 32x64.
// smem: A 65536 | B 5*32768 = 229376 bytes.
// =============================================================================
#define A_BYTES  65536
#define BSTG_B   32768
#define NSTG     5
#define GEMM_SMEM (A_BYTES + NSTG * BSTG_B)

__global__ __launch_bounds__(512, 1) void gemm_mma_kernel()
{
    extern __shared__ char sm[];
    const uint32_t sb = smem_u32(sm);
    __shared__ float sd[64], sd2[64];

    const int tid  = threadIdx.x;
    const int warp = tid >> 5;
    const int lane = tid & 31;
    const int wm   = (warp >> 2) * 32;     // warp M origin 0..96
    const int wn   = (warp & 3) * 64;      // warp N origin 0..192

    const int blk  = blockIdx.x;
    const int p    = blk & 1;
    const int row0 = (blk >> 1) * 128;
    const int jb   = p ? 1024 : 0;

    const __half* __restrict__ Xh = g_Xh + (size_t)p * NXF;

    if (tid < 64) { sd[tid] = 0.f; sd2[tid] = 0.f; }

    float acc[2][8][4];
    #pragma unroll
    for (int a = 0; a < 2; a++)
        #pragma unroll
        for (int b = 0; b < 8; b++)
            #pragma unroll
            for (int c = 0; c < 4; c++) acc[a][b][c] = 0.f;

    // ---- A resident load: thread -> row r=tid>>2, chunks (tid&3)*8 .. +7 -----
    {
        const int r   = tid >> 2;
        const int cb0 = (tid & 3) * 8;
        const __half* s0 = Xh + (size_t)(row0 + r) * 256;
        const uint32_t rb = sb + r * 512;
        #pragma unroll
        for (int q = 0; q < 8; q++) {
            int ch = cb0 + q;
            uint32_t sw = (uint32_t)((ch & 24) | ((ch ^ (r & 7)) & 7)) << 4;
            CP16(rb + sw, s0 + ch * 8);
        }
    }

    // ---- B chunk issue --------------------------------------------------------
    const int lr = tid >> 1;            // 0..255
    const int cb = (tid & 1) * 4;
    auto issueB = [&](int g, int st) {
        const int tile  = g >> 2;
        const int kc    = g & 3;
        const int which = p + 2 * (tile >> 2);
        const int col0  = (tile & 3) * 256;
        const __half* Wb = g_Wh + (size_t)which * NWF +
                           (size_t)(col0 + lr) * 256 + kc * 64 + cb * 8;
        uint32_t d0 = sb + A_BYTES + st * BSTG_B + lr * 128;
        #pragma unroll
        for (int q = 0; q < 4; q++) {
            uint32_t sw = (uint32_t)((cb + q) ^ (lr & 7)) << 4;
            CP16(d0 + sw, Wb + q * 8);
        }
    };

    issueB(0, 0); CP_COMMIT();   // group0 = A + B0
    issueB(1, 1); CP_COMMIT();
    issueB(2, 2); CP_COMMIT();
    issueB(3, 3); CP_COMMIT();

    const int rlo   = lane >> 2;
    const int cpair = (lane & 3) * 2;
    const int lrow  = lane & 15;
    const int lhalf = lane >> 4;

    for (int g = 0; g < 32; g++) {
        if (g <= 27) { CP_WAIT3(); } else { CP_WAIT0(); }
        __syncthreads();
        if (g + 4 < 32) { issueB(g + 4, (g + 4) % NSTG); CP_COMMIT(); }

        const int kc = g & 3;
        const uint32_t bstg = sb + A_BYTES + (g % NSTG) * BSTG_B;

        #pragma unroll
        for (int k16 = 0; k16 < 4; k16++) {
            uint32_t ah[2][4];
            #pragma unroll
            for (int mf = 0; mf < 2; mf++) {
                int r  = wm + mf * 16 + lrow;
                int ch = kc * 8 + 2 * k16 + lhalf;
                uint32_t sw = (uint32_t)((ch & 24) | ((ch ^ (r & 7)) & 7)) << 4;
                LDSM4(ah[mf][0], ah[mf][1], ah[mf][2], ah[mf][3], sb + r * 512 + sw);
            }
            #pragma unroll
            for (int j = 0; j < 4; j++) {
                int r  = wn + j * 16 + lrow;
                int ch = 2 * k16 + lhalf;
                uint32_t bd = bstg + r * 128 + ((uint32_t)((ch ^ (r & 7)) & 7) << 4);
                uint32_t b0, b1, b2, b3;
                LDSM4(b0, b1, b2, b3, bd);
                #pragma unroll
                for (int mf = 0; mf < 2; mf++) {
                    MMA16816(acc[mf][2 * j],     ah[mf], b0, b2);
                    MMA16816(acc[mf][2 * j + 1], ah[mf], b1, b3);
                }
            }
        }

        if ((g & 3) == 3) {
            // -------- tile epilogue: store + (K tiles) stats ------------------
            const int tile  = g >> 2;
            const int which = p + 2 * (tile >> 2);
            const int col0  = (tile & 3) * 256;
            if (which < 2) {
                // K: fp16 store + stats
                #pragma unroll
                for (int mf = 0; mf < 2; mf++) {
                    #pragma unroll
                    for (int nf = 0; nf < 8; nf++) {
                        int row = row0 + wm + mf * 16 + rlo;
                        int col = jb + col0 + wn + nf * 8 + cpair;
                        *(__half2*)(g_Kh + (size_t)row * 2048 + col) =
                            __floats2half2_rn(acc[mf][nf][0], acc[mf][nf][1]);
                        *(__half2*)(g_Kh + (size_t)(row + 8) * 2048 + col) =
                            __floats2half2_rn(acc[mf][nf][2], acc[mf][nf][3]);
                    }
                }
                #pragma unroll
                for (int nf = 0; nf < 8; nf++) {
                    float s0 = 0.f, s1 = 0.f, q0 = 0.f, q1 = 0.f;
                    #pragma unroll
                    for (int mf = 0; mf < 2; mf++) {
                        float a0 = acc[mf][nf][0], a1 = acc[mf][nf][1];
                        float a2 = acc[mf][nf][2], a3 = acc[mf][nf][3];
                        s0 += a0 + a2;  s1 += a1 + a3;
                        q0 += a0 * a0 + a2 * a2;
                        q1 += a1 * a1 + a3 * a3;
                    }
                    #pragma unroll
                    for (int o = 4; o <= 16; o <<= 1) {
                        s0 += __shfl_xor_sync(0xffffffffu, s0, o);
                        s1 += __shfl_xor_sync(0xffffffffu, s1, o);
                        q0 += __shfl_xor_sync(0xffffffffu, q0, o);
                        q1 += __shfl_xor_sync(0xffffffffu, q1, o);
                    }
                    if (lane < 4) {
                        int d = (wn + nf * 8 + lane * 2) & 63;
                        atomicAdd(&sd[d], s0);   atomicAdd(&sd[d + 1], s1);
                        atomicAdd(&sd2[d], q0);  atomicAdd(&sd2[d + 1], q1);
                    }
                }
            } else {
                // V: fp32 store
                #pragma unroll
                for (int mf = 0; mf < 2; mf++) {
                    #pragma unroll
                    for (int nf = 0; nf < 8; nf++) {
                        int row = row0 + wm + mf * 16 + rlo;
                        int col = jb + col0 + wn + nf * 8 + cpair;
                        *(float2*)(g_V + (size_t)row * 2048 + col) =
                            make_float2(acc[mf][nf][0], acc[mf][nf][1]);
                        *(float2*)(g_V + (size_t)(row + 8) * 2048 + col) =
                            make_float2(acc[mf][nf][2], acc[mf][nf][3]);
                    }
                }
            }
            #pragma unroll
            for (int a = 0; a < 2; a++)
                #pragma unroll
                for (int b = 0; b < 8; b++)
                    #pragma unroll
                    for (int c2 = 0; c2 < 4; c2++) acc[a][b][c2] = 0.f;
        }
    }

    __syncthreads();
    if (tid < 64) {
        atomicAdd(&g_sumK[tid], sd[tid]);
        atomicAdd(&g_sumK2[tid], sd2[tid]);
    }
}

// ---------------- fold BN stats into per-d affine constants ------------------
__global__ void finalize_kernel(const float* __restrict__ Wq,
                                const float* __restrict__ gammaQ,
                                const float* __restrict__ betaQ,
                                const float* __restrict__ gammaK,
                                const float* __restrict__ betaK)
{
    int d = threadIdx.x;
    if (d >= 64) return;
    const float invB = 1.f / 65536.f;

    float w[4];
    #pragma unroll
    for (int c = 0; c < 4; c++) w[c] = Wq[d * 4 + c];

    float mQ = 0.f;
    #pragma unroll
    for (int c = 0; c < 4; c++) mQ += (g_cmd[c] * invB) * w[c];
    float eq2 = 0.f;
    #pragma unroll
    for (int c1 = 0; c1 < 4; c1++)
        #pragma unroll
        for (int c2 = 0; c2 < 4; c2++)
            eq2 += w[c1] * w[c2] * g_cmd[4 + c1 * 4 + c2];
    eq2 *= invB;
    float vQ = eq2 - mQ * mQ;
    float gq = gammaQ[d] / sqrtf(vQ + EPS);
    g_cst[d]      = gq;
    g_cst[64 + d] = betaQ[d] - mQ * gq;

    const float invBF = 1.f / (65536.f * 32.f);
    float mK = g_sumK[d] * invBF;
    float vK = g_sumK2[d] * invBF - mK * mK;
    float aK = gammaK[d] / sqrtf(vK + EPS);
    g_cst[128 + d] = aK;
    g_cst[192 + d] = betaK[d] - mK * aK;
}

// ---------------- attention: 1 warp per batch row -----------------------------
__global__ __launch_bounds__(256) void attn_kernel(
    const float* __restrict__ command, const float* __restrict__ Wq,
    float* __restrict__ out)
{
    __shared__ float sh_qa[8][64];
    const int w    = threadIdx.x >> 5;
    const int lane = threadIdx.x & 31;
    const int b    = blockIdx.x * 8 + w;

    float4 c4 = *(const float4*)(command + (size_t)b * 4);
    const int d0 = lane, d1 = lane + 32;

    float q0 = c4.x * Wq[d0 * 4 + 0] + c4.y * Wq[d0 * 4 + 1] +
               c4.z * Wq[d0 * 4 + 2] + c4.w * Wq[d0 * 4 + 3];
    float q1 = c4.x * Wq[d1 * 4 + 0] + c4.y * Wq[d1 * 4 + 1] +
               c4.z * Wq[d1 * 4 + 2] + c4.w * Wq[d1 * 4 + 3];
    float qn0 = q0 * g_cst[d0] + g_cst[64 + d0];
    float qn1 = q1 * g_cst[d1] + g_cst[64 + d1];

    float qa0 = qn0 * g_cst[128 + d0];
    float qa1 = qn1 * g_cst[128 + d1];
    float qc  = qn0 * g_cst[192 + d0] + qn1 * g_cst[192 + d1];
    #pragma unroll
    for (int o = 16; o; o >>= 1) qc += __shfl_xor_sync(0xffffffffu, qc, o);

    sh_qa[w][d0] = qa0;
    sh_qa[w][d1] = qa1;
    __syncwarp();

    // logit for f = lane: dot(qa, K[b, f*64 .. f*64+63])  (K fp16, contiguous)
    const __half2* Kr = (const __half2*)(g_Kh + (size_t)b * 2048 + lane * 64);
    float acc = 0.f;
    #pragma unroll
    for (int t = 0; t < 32; t++) {
        float2 kf = __half22float2(Kr[t]);
        acc += sh_qa[w][2 * t] * kf.x + sh_qa[w][2 * t + 1] * kf.y;
    }
    float logit = (acc + qc) * 0.125f;

    float mx = logit;
    #pragma unroll
    for (int o = 16; o; o >>= 1) mx = fmaxf(mx, __shfl_xor_sync(0xffffffffu, mx, o));
    float e = __expf(logit - mx);
    float den = e;
    #pragma unroll
    for (int o = 16; o; o >>= 1) den += __shfl_xor_sync(0xffffffffu, den, o);
    float a = e / den;

    const float* Vr = g_V + (size_t)b * 2048;
    float s0 = 0.f, s1 = 0.f;
    #pragma unroll
    for (int f = 0; f < 32; f++) {
        float af = __shfl_sync(0xffffffffu, a, f);
        s0 += af * Vr[f * 64 + d0];
        s1 += af * Vr[f * 64 + d1];
    }
    out[(size_t)b * 64 + d0] = s0;
    out[(size_t)b * 64 + d1] = s1;
}

// ---------------- launch ------------------------------------------------------
extern "C" void kernel_launch(void* const* d_in, const int* in_sizes, int n_in,
                              void* d_out, int out_size)
{
    const float* feature = (const float*)d_in[0];
    const float* hidden  = (const float*)d_in[1];
    const float* command = (const float*)d_in[2];
    const float* Wq      = (const float*)d_in[3];
    const float* Wkz     = (const float*)d_in[4];
    const float* Wkh     = (const float*)d_in[5];
    const float* Wvz     = (const float*)d_in[6];
    const float* Wvh     = (const float*)d_in[7];
    const float* gammaQ  = (const float*)d_in[8];
    const float* betaQ   = (const float*)d_in[9];
    const float* gammaK  = (const float*)d_in[10];
    const float* betaK   = (const float*)d_in[11];
    float* out = (float*)d_out;

    cudaFuncSetAttribute(gemm_mma_kernel,
                         cudaFuncAttributeMaxDynamicSharedMemorySize, GEMM_SMEM);

    zero_stats_kernel<<<1, 64>>>();
    cmd_stats_kernel<<<128, 256>>>(command);
    split_kernel<<<33792, 256>>>(feature, hidden, Wkz, Wkh, Wvz, Wvh);
    gemm_mma_kernel<<<1024, 512, GEMM_SMEM>>>();
    finalize_kernel<<<1, 64>>>(Wq, gammaQ, betaQ, gammaK, betaK);
    attn_kernel<<<B_TOT / 8, 256>>>(command, Wq, out);
}